// round 15
// baseline (speedup 1.0000x reference)
#include <cuda_runtime.h>
#include <cuda_fp16.h>
#include <cstdint>

// Problem constants
#define Bsz 16
#define Sl  2048
#define Hd  768
#define NT        (Bsz*(Sl-1))   // 32752 tokens for GEMMs
#define NTOK_FULL (Bsz*Sl)       // 32768

// Scratch (device globals)
__device__ __half g_sequ_h[(size_t)NTOK_FULL*Hd]; // fp16(seqs + E_u[u])
__device__ __half g_ph [(size_t)NT*Hd];           // relu(pairs @ W_hid^T)
__device__ __half g_dc [(size_t)NT*128];          // relu(cat @ W_cd^T)
__device__ __half g_m  [(size_t)NT*Hd];           // relu(cat @ W_cdh^T)

// fp16 weight / embedding copies
__device__ __half g_Ed  [512*128];
__device__ __half g_Ec  [512*128];
__device__ __half g_Wcd [128*256];
__device__ __half g_Whid[768*1536];
__device__ __half g_Wcdh[768*896];

__device__ __forceinline__ float4 ld4(const float* p){
    return *reinterpret_cast<const float4*>(p);
}
__device__ __forceinline__ void cpa16(uint32_t dst, const void* src){
    asm volatile("cp.async.cg.shared.global [%0], [%1], 16;\n" :: "r"(dst), "l"(src));
}
#define LDSM_X4(r0,r1,r2,r3,addr) \
    asm volatile("ldmatrix.sync.aligned.m8n8.x4.shared.b16 {%0,%1,%2,%3}, [%4];" \
        : "=r"(r0),"=r"(r1),"=r"(r2),"=r"(r3) : "r"(addr))

// ---------------------------------------------------------------------------
// Prep: fp16-convert three tensors in one launch
// ---------------------------------------------------------------------------
__global__ void halftri_k(__half* d0, const float* s0, int n0,
                          __half* d1, const float* s1, int n1,
                          __half* d2, const float* s2, int n2){
    int i = (blockIdx.x*blockDim.x + threadIdx.x)*4;
    const float* s; __half* d; int j = i;
    if (j < n0){ s = s0; d = d0; }
    else { j -= n0;
        if (j < n1){ s = s1; d = d1; }
        else { j -= n1; if (j >= n2) return; s = s2; d = d2; }
    }
    float4 v = ld4(s + j);
    __half2* o = reinterpret_cast<__half2*>(d + j);
    o[0] = __floats2half2_rn(v.x, v.y);
    o[1] = __floats2half2_rn(v.z, v.w);
}

// ---------------------------------------------------------------------------
// seqs_u = fp16(seqs + E_u[u]); 2 rows/block, 96 thr/row, 8 el/thr
// tbase: first token handled by block 0.
// ---------------------------------------------------------------------------
__global__ void add_ue_k(const float* __restrict__ seqs,
                         const int*   __restrict__ u,
                         const float* __restrict__ Eu, int tbase){
    int half = threadIdx.x / 96;
    int j    = threadIdx.x % 96;
    int t = tbase + blockIdx.x*2 + half;
    int uid = __ldg(&u[t]);
    const float4* s4 = reinterpret_cast<const float4*>(seqs + (size_t)t*Hd)   + j*2;
    const float4* e4 = reinterpret_cast<const float4*>(Eu   + (size_t)uid*Hd) + j*2;
    float4 a0 = s4[0], a1 = s4[1];
    float4 b0 = e4[0], b1 = e4[1];
    __half2 o[4];
    o[0] = __floats2half2_rn(a0.x+b0.x, a0.y+b0.y);
    o[1] = __floats2half2_rn(a0.z+b0.z, a0.w+b0.w);
    o[2] = __floats2half2_rn(a1.x+b1.x, a1.y+b1.y);
    o[3] = __floats2half2_rn(a1.z+b1.z, a1.w+b1.w);
    *reinterpret_cast<uint4*>(g_sequ_h + (size_t)t*Hd + j*8) =
        *reinterpret_cast<const uint4*>(o);
}

// ---------------------------------------------------------------------------
// FP16 tensor-core GEMM (mma.sync m16n8k16, f32 acc), 3-stage cp.async pipe,
// double-buffered LDSM fragments (round-13 plateau config — do not touch).
// mbase: M-block offset (m0 = (mbase + blockIdx.y)*128).
// MODE 0: A = [g_Ed[d[t]] | g_Ec[c[t]]],  K=256,  OUT=128 -> g_dc
// MODE 1: A = g_sequ_h pairs,             K=1536, OUT=768 -> g_ph
// MODE 2: A = [g_ph | g_dc],              K=896,  OUT=768 -> g_m
// ---------------------------------------------------------------------------
#define KTILE 64
#define SSTR  36                      // u32 stride per row
#define TILE_U32 (128*SSTR)           // 4608 words
#define TILE_B   (TILE_U32*4)         // 18432 bytes
#define STAGES   3
#define SMEM_TOT (STAGES*2*TILE_B)    // 110592 bytes -> 2 CTAs/SM

template<int MODE, int K, int OUT>
__global__ __launch_bounds__(256, 2)
void gemm_f16_k(const int* __restrict__ I0, const int* __restrict__ I1,
                const __half* __restrict__ W, int mbase){
    extern __shared__ uint32_t smem[];
    const uint32_t sbase = (uint32_t)__cvta_generic_to_shared(smem);

    const int tid  = threadIdx.x;
    const int lane = tid & 31;
    const int warp = tid >> 5;
    const int m0   = (mbase + blockIdx.y) * 128;
    const int n0   = blockIdx.x * 128;
    const int wm   = (warp >> 1) * 32;
    const int wn   = (warp &  1) * 64;
    const int g    = lane >> 2;
    const int c    = lane &  3;

    const uint32_t aoff0 = (uint32_t)(((wm + (lane & 7) + ((lane >> 3) & 1)*8)*SSTR
                                      + ((lane >> 4) & 1)*4))*4;
    const uint32_t boff0 = (uint32_t)(((wn + (lane & 7) + ((lane >> 4) & 1)*8)*SSTR
                                      + ((lane >> 3) & 1)*4))*4;

    auto issue_tile = [&](int ch){
        uint32_t aB = sbase + (uint32_t)(ch % STAGES)*2*TILE_B;
        uint32_t bB = aB + TILE_B;
        const int k0 = ch*KTILE;
        #pragma unroll
        for (int it = 0; it < 4; it++){
            int idx = tid + it*256;
            int r   = idx >> 3;
            int kq  = (idx & 7) << 3;
            int t = m0 + r; if (t > NT-1) t = NT-1;
            const __half* sa;
            if (MODE == 0){
                sa = (k0 < 128)
                   ? g_Ed + (size_t)__ldg(&I0[t])*128 + kq + k0
                   : g_Ec + (size_t)__ldg(&I1[t])*128 + kq + (k0 - 128);
            } else if (MODE == 1){
                int row = t + t/2047;   // b*2048 + s from t = b*2047 + s
                sa = g_sequ_h + (size_t)row*Hd + kq + k0;
            } else {
                sa = (k0 < 768)
                   ? g_ph + (size_t)t*768 + kq + k0
                   : g_dc + (size_t)t*128 + kq + (k0 - 768);
            }
            uint32_t doff = (uint32_t)(r*SSTR*4 + kq*2);
            cpa16(aB + doff, sa);
            cpa16(bB + doff, W + (size_t)(n0 + r)*K + kq + k0);
        }
        asm volatile("cp.async.commit_group;\n" ::);
    };

    float acc[2][8][4];
    #pragma unroll
    for (int mi = 0; mi < 2; mi++)
        #pragma unroll
        for (int ni = 0; ni < 8; ni++)
            #pragma unroll
            for (int q = 0; q < 4; q++) acc[mi][ni][q] = 0.f;

    uint32_t afr[2][2][4], bfr[2][8][2];

    constexpr int NTILES = K / KTILE;
    issue_tile(0);
    if (NTILES > 1) issue_tile(1);

    for (int ti = 0; ti < NTILES; ti++){
        if (ti + 2 < NTILES) issue_tile(ti + 2);

        int pend = NTILES - 1 - ti; if (pend > 2) pend = 2;
        if      (pend == 2) asm volatile("cp.async.wait_group 2;\n" ::);
        else if (pend == 1) asm volatile("cp.async.wait_group 1;\n" ::);
        else                asm volatile("cp.async.wait_group 0;\n" ::);
        __syncthreads();

        const uint32_t aBase = sbase + (uint32_t)(ti % STAGES)*2*TILE_B + aoff0;
        const uint32_t bBase = sbase + (uint32_t)(ti % STAGES)*2*TILE_B + TILE_B + boff0;

        #pragma unroll
        for (int mi = 0; mi < 2; mi++)
            LDSM_X4(afr[0][mi][0], afr[0][mi][1], afr[0][mi][2], afr[0][mi][3],
                    aBase + mi*(16*SSTR*4));
        #pragma unroll
        for (int nj = 0; nj < 4; nj++)
            LDSM_X4(bfr[0][2*nj][0], bfr[0][2*nj][1], bfr[0][2*nj+1][0], bfr[0][2*nj+1][1],
                    bBase + nj*(16*SSTR*4));

        #pragma unroll
        for (int s = 0; s < 3; s++){
            const int nb = (s + 1) & 1;
            const int cb = s & 1;
            #pragma unroll
            for (int mi = 0; mi < 2; mi++)
                LDSM_X4(afr[nb][mi][0], afr[nb][mi][1], afr[nb][mi][2], afr[nb][mi][3],
                        aBase + mi*(16*SSTR*4) + (s+1)*32);
            #pragma unroll
            for (int nj = 0; nj < 4; nj++)
                LDSM_X4(bfr[nb][2*nj][0], bfr[nb][2*nj][1],
                        bfr[nb][2*nj+1][0], bfr[nb][2*nj+1][1],
                        bBase + nj*(16*SSTR*4) + (s+1)*32);
            #pragma unroll
            for (int mi = 0; mi < 2; mi++)
                #pragma unroll
                for (int ni = 0; ni < 8; ni++){
                    asm volatile(
                        "mma.sync.aligned.m16n8k16.row.col.f32.f16.f16.f32 "
                        "{%0,%1,%2,%3}, {%4,%5,%6,%7}, {%8,%9}, {%0,%1,%2,%3};\n"
                        : "+f"(acc[mi][ni][0]), "+f"(acc[mi][ni][1]),
                          "+f"(acc[mi][ni][2]), "+f"(acc[mi][ni][3])
                        : "r"(afr[cb][mi][0]), "r"(afr[cb][mi][1]),
                          "r"(afr[cb][mi][2]), "r"(afr[cb][mi][3]),
                          "r"(bfr[cb][ni][0]), "r"(bfr[cb][ni][1]));
                }
        }
        #pragma unroll
        for (int mi = 0; mi < 2; mi++)
            #pragma unroll
            for (int ni = 0; ni < 8; ni++){
                asm volatile(
                    "mma.sync.aligned.m16n8k16.row.col.f32.f16.f16.f32 "
                    "{%0,%1,%2,%3}, {%4,%5,%6,%7}, {%8,%9}, {%0,%1,%2,%3};\n"
                    : "+f"(acc[mi][ni][0]), "+f"(acc[mi][ni][1]),
                      "+f"(acc[mi][ni][2]), "+f"(acc[mi][ni][3])
                    : "r"(afr[1][mi][0]), "r"(afr[1][mi][1]),
                      "r"(afr[1][mi][2]), "r"(afr[1][mi][3]),
                      "r"(bfr[1][ni][0]), "r"(bfr[1][ni][1]));
            }
        __syncthreads();
    }

    // Epilogue: ReLU, fp16 store
    __half* Ch = (MODE == 0) ? g_dc : (MODE == 1) ? g_ph : g_m;
    #pragma unroll
    for (int mi = 0; mi < 2; mi++){
        int rbase = m0 + wm + mi*16 + g;
        #pragma unroll
        for (int half = 0; half < 2; half++){
            int t = rbase + half*8;
            if (t < NT){
                int col = n0 + wn + 2*c;
                #pragma unroll
                for (int ni = 0; ni < 8; ni++){
                    float x = fmaxf(acc[mi][ni][half*2 + 0], 0.f);
                    float y = fmaxf(acc[mi][ni][half*2 + 1], 0.f);
                    *reinterpret_cast<__half2*>(
                        Ch + (size_t)t*OUT + col + ni*8) = __floats2half2_rn(x, y);
                }
            }
        }
    }
}

// ---------------------------------------------------------------------------
// Final: out[b,s] = sequ_h[b,s] + (s<S-1 ? m[b,s] : 0) + (s>=2 ? m[b,s-1] : 0)
// tbase: first token handled by block 0 (must be multiple of 2048).
// ---------------------------------------------------------------------------
__global__ void final_k(float* __restrict__ out, int tbase){
    int half = threadIdx.x / 96;
    int j    = threadIdx.x % 96;
    int t = tbase + blockIdx.x*2 + half;
    int s = t & (Sl - 1);
    int b = t >> 11;

    uint4 sqv = *reinterpret_cast<const uint4*>(g_sequ_h + (size_t)t*Hd + j*8);
    const __half2* sq = reinterpret_cast<const __half2*>(&sqv);
    float2 v[4];
    #pragma unroll
    for (int q = 0; q < 4; q++) v[q] = __half22float2(sq[q]);

    size_t mb = (size_t)b * (Sl - 1);
    if (s < Sl - 1){
        uint4 mv = *reinterpret_cast<const uint4*>(g_m + (mb + s)*Hd + j*8);
        const __half2* mp = reinterpret_cast<const __half2*>(&mv);
        #pragma unroll
        for (int q = 0; q < 4; q++){
            float2 f = __half22float2(mp[q]);
            v[q].x += f.x; v[q].y += f.y;
        }
    }
    if (s >= 2){
        uint4 mv = *reinterpret_cast<const uint4*>(g_m + (mb + s - 1)*Hd + j*8);
        const __half2* mp = reinterpret_cast<const __half2*>(&mv);
        #pragma unroll
        for (int q = 0; q < 4; q++){
            float2 f = __half22float2(mp[q]);
            v[q].x += f.x; v[q].y += f.y;
        }
    }
    float* op = out + (size_t)t*Hd + j*8;
    *reinterpret_cast<float4*>(op)     = make_float4(v[0].x, v[0].y, v[1].x, v[1].y);
    *reinterpret_cast<float4*>(op + 4) = make_float4(v[2].x, v[2].y, v[3].x, v[3].y);
}

// ---------------------------------------------------------------------------
// Launch: split-pipeline fork/join.
//   main: add_ueH0 -> gemm1H0 -> gemm1H1 -> gemm2H0 -> gemm2H1 -> finalH1
//   s1:   prep(W) -> add_ueH1 -> prep(E) -> gemm0 -> [wait g2H0] finalH0
// ---------------------------------------------------------------------------
#define AU_H0_BLK 8200                 // tokens 0..16399 (covers gemm1H0 rows)
#define AU_H1_BLK (NTOK_FULL/2 - AU_H0_BLK)

extern "C" void kernel_launch(void* const* d_in, const int* in_sizes, int n_in,
                              void* d_out, int out_size){
    const float* seqs  = (const float*)d_in[0];
    const int*   d_idx = (const int*)  d_in[1];
    const int*   c_idx = (const int*)  d_in[2];
    const int*   u_idx = (const int*)  d_in[3];
    const float* E_d   = (const float*)d_in[4];
    const float* E_c   = (const float*)d_in[5];
    const float* E_u   = (const float*)d_in[6];
    const float* W_cd  = (const float*)d_in[7];
    const float* W_hid = (const float*)d_in[8];
    const float* W_cdh = (const float*)d_in[9];
    float* out = (float*)d_out;

    static cudaStream_t s1 = nullptr;
    static cudaEvent_t evFork = nullptr, evWhid = nullptr, evAU1 = nullptr,
                       evG0 = nullptr, evG2H0 = nullptr, evF0 = nullptr;
    if (!s1){
        cudaStreamCreateWithFlags(&s1, cudaStreamNonBlocking);
        cudaEventCreateWithFlags(&evFork, cudaEventDisableTiming);
        cudaEventCreateWithFlags(&evWhid, cudaEventDisableTiming);
        cudaEventCreateWithFlags(&evAU1,  cudaEventDisableTiming);
        cudaEventCreateWithFlags(&evG0,   cudaEventDisableTiming);
        cudaEventCreateWithFlags(&evG2H0, cudaEventDisableTiming);
        cudaEventCreateWithFlags(&evF0,   cudaEventDisableTiming);

        cudaFuncSetAttribute(gemm_f16_k<0,256,128>,  cudaFuncAttributeMaxDynamicSharedMemorySize, SMEM_TOT);
        cudaFuncSetAttribute(gemm_f16_k<1,1536,768>, cudaFuncAttributeMaxDynamicSharedMemorySize, SMEM_TOT);
        cudaFuncSetAttribute(gemm_f16_k<2,896,768>,  cudaFuncAttributeMaxDynamicSharedMemorySize, SMEM_TOT);
    }

    __half *pEd, *pEc, *pWcd, *pWhid, *pWcdh;
    cudaGetSymbolAddress((void**)&pEd,   g_Ed);
    cudaGetSymbolAddress((void**)&pEc,   g_Ec);
    cudaGetSymbolAddress((void**)&pWcd,  g_Wcd);
    cudaGetSymbolAddress((void**)&pWhid, g_Whid);
    cudaGetSymbolAddress((void**)&pWcdh, g_Wcdh);

    // ---- fork
    cudaEventRecord(evFork, 0);
    cudaStreamWaitEvent(s1, evFork, 0);

    // s1: weight prep first (unblocks gemm1H0 early)
    {
        int n0 = 768*1536, n1 = 768*896, n2 = 128*256;
        halftri_k<<<((n0+n1+n2)/4 + 255)/256, 256, 0, s1>>>(
            pWhid, W_hid, n0, pWcdh, W_cdh, n1, pWcd, W_cd, n2);
    }
    cudaEventRecord(evWhid, s1);
    // s1: add_ue H1 (tokens 16400..32767)
    add_ue_k<<<AU_H1_BLK, 192, 0, s1>>>(seqs, u_idx, E_u, AU_H0_BLK*2);
    cudaEventRecord(evAU1, s1);
    // s1: embedding prep + gemm0
    {
        int n0 = 512*128, n1 = 512*128;
        halftri_k<<<((n0+n1)/4 + 255)/256, 256, 0, s1>>>(
            pEd, E_d, n0, pEc, E_c, n1, nullptr, nullptr, 0);
    }
    gemm_f16_k<0, 256, 128><<<dim3(1, 256), 256, SMEM_TOT, s1>>>(d_idx, c_idx, pWcd, 0);
    cudaEventRecord(evG0, s1);

    // main: add_ue H0 (tokens 0..16399)
    add_ue_k<<<AU_H0_BLK, 192>>>(seqs, u_idx, E_u, 0);

    // gemm1 H0 (M-blocks 0..127): needs Whid + add_ueH0
    cudaStreamWaitEvent(0, evWhid, 0);
    gemm_f16_k<1, 1536, 768><<<dim3(6, 128), 256, SMEM_TOT>>>(nullptr, nullptr, pWhid, 0);

    // gemm1 H1 (M-blocks 128..255): additionally needs add_ueH1
    cudaStreamWaitEvent(0, evAU1, 0);
    gemm_f16_k<1, 1536, 768><<<dim3(6, 128), 256, SMEM_TOT>>>(nullptr, nullptr, pWhid, 128);

    // gemm2 H0: needs gemm1 (stream order) + gemm0
    cudaStreamWaitEvent(0, evG0, 0);
    gemm_f16_k<2, 896, 768><<<dim3(6, 128), 256, SMEM_TOT>>>(nullptr, nullptr, pWcdh, 0);
    cudaEventRecord(evG2H0, 0);

    // s1: final H0 (batches 0..7; m rows <= 16375 < 16384) overlaps gemm2H1
    cudaStreamWaitEvent(s1, evG2H0, 0);
    final_k<<<8192, 192, 0, s1>>>(out, 0);
    cudaEventRecord(evF0, s1);

    // main: gemm2 H1
    gemm_f16_k<2, 896, 768><<<dim3(6, 128), 256, SMEM_TOT>>>(nullptr, nullptr, pWcdh, 128);

    // main: join s1, then final H1 (batches 8..15)
    cudaStreamWaitEvent(0, evF0, 0);
    final_k<<<8192, 192>>>(out, 16384);
}

// round 16
// speedup vs baseline: 1.0747x; 1.0747x over previous
#include <cuda_runtime.h>
#include <cuda_fp16.h>
#include <cstdint>

// Problem constants
#define Bsz 16
#define Sl  2048
#define Hd  768
#define NT        (Bsz*(Sl-1))   // 32752 tokens for GEMMs
#define NTOK_FULL (Bsz*Sl)       // 32768

// Scratch (device globals)
__device__ __half g_sequ_h[(size_t)NTOK_FULL*Hd]; // fp16(seqs + E_u[u])
__device__ __half g_ph [(size_t)NT*Hd];           // relu(pairs @ W_hid^T)
__device__ __half g_dc [(size_t)NT*128];          // relu(cat @ W_cd^T)
__device__ __half g_m  [(size_t)NT*Hd];           // relu(cat @ W_cdh^T)

// fp16 weight / embedding copies
__device__ __half g_Ed  [512*128];
__device__ __half g_Ec  [512*128];
__device__ __half g_Wcd [128*256];
__device__ __half g_Whid[768*1536];
__device__ __half g_Wcdh[768*896];

__device__ __forceinline__ float4 ld4(const float* p){
    return *reinterpret_cast<const float4*>(p);
}
__device__ __forceinline__ void cpa16(uint32_t dst, const void* src){
    asm volatile("cp.async.cg.shared.global [%0], [%1], 16;\n" :: "r"(dst), "l"(src));
}
__device__ __forceinline__ void stg_cs16(float* p, float4 v){
    asm volatile("st.global.cs.v4.f32 [%0], {%1,%2,%3,%4};"
                 :: "l"(p), "f"(v.x), "f"(v.y), "f"(v.z), "f"(v.w) : "memory");
}
#define LDSM_X4(r0,r1,r2,r3,addr) \
    asm volatile("ldmatrix.sync.aligned.m8n8.x4.shared.b16 {%0,%1,%2,%3}, [%4];" \
        : "=r"(r0),"=r"(r1),"=r"(r2),"=r"(r3) : "r"(addr))

// ---------------------------------------------------------------------------
// Prep: fp16-convert up to five tensors in one launch (W tensors first so the
// downstream event covers them as early as possible).
// ---------------------------------------------------------------------------
__global__ void halfquint_k(__half* d0, const float* s0, int n0,
                            __half* d1, const float* s1, int n1,
                            __half* d2, const float* s2, int n2,
                            __half* d3, const float* s3, int n3,
                            __half* d4, const float* s4, int n4){
    int i = (blockIdx.x*blockDim.x + threadIdx.x)*4;
    const float* s; __half* d; int j = i;
    if (j < n0){ s = s0; d = d0; }
    else { j -= n0;
      if (j < n1){ s = s1; d = d1; }
      else { j -= n1;
        if (j < n2){ s = s2; d = d2; }
        else { j -= n2;
          if (j < n3){ s = s3; d = d3; }
          else { j -= n3; if (j >= n4) return; s = s4; d = d4; }
        }
      }
    }
    float4 v = ld4(s + j);
    __half2* o = reinterpret_cast<__half2*>(d + j);
    o[0] = __floats2half2_rn(v.x, v.y);
    o[1] = __floats2half2_rn(v.z, v.w);
}

// ---------------------------------------------------------------------------
// seqs_u = fp16(seqs + E_u[u]); 2 rows/block, 96 thr/row, 8 el/thr
// ---------------------------------------------------------------------------
__global__ void add_ue_k(const float* __restrict__ seqs,
                         const int*   __restrict__ u,
                         const float* __restrict__ Eu){
    int half = threadIdx.x / 96;
    int j    = threadIdx.x % 96;
    int t = blockIdx.x*2 + half;
    int uid = __ldg(&u[t]);
    const float4* s4 = reinterpret_cast<const float4*>(seqs + (size_t)t*Hd)   + j*2;
    const float4* e4 = reinterpret_cast<const float4*>(Eu   + (size_t)uid*Hd) + j*2;
    float4 a0 = s4[0], a1 = s4[1];
    float4 b0 = e4[0], b1 = e4[1];
    __half2 o[4];
    o[0] = __floats2half2_rn(a0.x+b0.x, a0.y+b0.y);
    o[1] = __floats2half2_rn(a0.z+b0.z, a0.w+b0.w);
    o[2] = __floats2half2_rn(a1.x+b1.x, a1.y+b1.y);
    o[3] = __floats2half2_rn(a1.z+b1.z, a1.w+b1.w);
    *reinterpret_cast<uint4*>(g_sequ_h + (size_t)t*Hd + j*8) =
        *reinterpret_cast<const uint4*>(o);
}

// ---------------------------------------------------------------------------
// FP16 tensor-core GEMM (mma.sync m16n8k16, f32 acc), 3-stage cp.async pipe,
// double-buffered LDSM fragments (round-13/14 plateau config — do not touch).
// MODE 0: A = [g_Ed[d[t]] | g_Ec[c[t]]],  K=256,  OUT=128 -> g_dc
// MODE 1: A = g_sequ_h pairs,             K=1536, OUT=768 -> g_ph
// MODE 2: A = [g_ph | g_dc],              K=896,  OUT=768 -> g_m
// ---------------------------------------------------------------------------
#define KTILE 64
#define SSTR  36                      // u32 stride per row
#define TILE_U32 (128*SSTR)           // 4608 words
#define TILE_B   (TILE_U32*4)         // 18432 bytes
#define STAGES   3
#define SMEM_TOT (STAGES*2*TILE_B)    // 110592 bytes -> 2 CTAs/SM

template<int MODE, int K, int OUT>
__global__ __launch_bounds__(256, 2)
void gemm_f16_k(const int* __restrict__ I0, const int* __restrict__ I1,
                const __half* __restrict__ W){
    extern __shared__ uint32_t smem[];
    const uint32_t sbase = (uint32_t)__cvta_generic_to_shared(smem);

    const int tid  = threadIdx.x;
    const int lane = tid & 31;
    const int warp = tid >> 5;
    const int m0   = blockIdx.y * 128;
    const int n0   = blockIdx.x * 128;
    const int wm   = (warp >> 1) * 32;
    const int wn   = (warp &  1) * 64;
    const int g    = lane >> 2;
    const int c    = lane &  3;

    const uint32_t aoff0 = (uint32_t)(((wm + (lane & 7) + ((lane >> 3) & 1)*8)*SSTR
                                      + ((lane >> 4) & 1)*4))*4;
    const uint32_t boff0 = (uint32_t)(((wn + (lane & 7) + ((lane >> 4) & 1)*8)*SSTR
                                      + ((lane >> 3) & 1)*4))*4;

    auto issue_tile = [&](int ch){
        uint32_t aB = sbase + (uint32_t)(ch % STAGES)*2*TILE_B;
        uint32_t bB = aB + TILE_B;
        const int k0 = ch*KTILE;
        #pragma unroll
        for (int it = 0; it < 4; it++){
            int idx = tid + it*256;
            int r   = idx >> 3;
            int kq  = (idx & 7) << 3;
            int t = m0 + r; if (t > NT-1) t = NT-1;
            const __half* sa;
            if (MODE == 0){
                sa = (k0 < 128)
                   ? g_Ed + (size_t)__ldg(&I0[t])*128 + kq + k0
                   : g_Ec + (size_t)__ldg(&I1[t])*128 + kq + (k0 - 128);
            } else if (MODE == 1){
                int row = t + t/2047;   // b*2048 + s from t = b*2047 + s
                sa = g_sequ_h + (size_t)row*Hd + kq + k0;
            } else {
                sa = (k0 < 768)
                   ? g_ph + (size_t)t*768 + kq + k0
                   : g_dc + (size_t)t*128 + kq + (k0 - 768);
            }
            uint32_t doff = (uint32_t)(r*SSTR*4 + kq*2);
            cpa16(aB + doff, sa);
            cpa16(bB + doff, W + (size_t)(n0 + r)*K + kq + k0);
        }
        asm volatile("cp.async.commit_group;\n" ::);
    };

    float acc[2][8][4];
    #pragma unroll
    for (int mi = 0; mi < 2; mi++)
        #pragma unroll
        for (int ni = 0; ni < 8; ni++)
            #pragma unroll
            for (int q = 0; q < 4; q++) acc[mi][ni][q] = 0.f;

    uint32_t afr[2][2][4], bfr[2][8][2];

    constexpr int NTILES = K / KTILE;
    issue_tile(0);
    if (NTILES > 1) issue_tile(1);

    for (int ti = 0; ti < NTILES; ti++){
        if (ti + 2 < NTILES) issue_tile(ti + 2);

        int pend = NTILES - 1 - ti; if (pend > 2) pend = 2;
        if      (pend == 2) asm volatile("cp.async.wait_group 2;\n" ::);
        else if (pend == 1) asm volatile("cp.async.wait_group 1;\n" ::);
        else                asm volatile("cp.async.wait_group 0;\n" ::);
        __syncthreads();

        const uint32_t aBase = sbase + (uint32_t)(ti % STAGES)*2*TILE_B + aoff0;
        const uint32_t bBase = sbase + (uint32_t)(ti % STAGES)*2*TILE_B + TILE_B + boff0;

        #pragma unroll
        for (int mi = 0; mi < 2; mi++)
            LDSM_X4(afr[0][mi][0], afr[0][mi][1], afr[0][mi][2], afr[0][mi][3],
                    aBase + mi*(16*SSTR*4));
        #pragma unroll
        for (int nj = 0; nj < 4; nj++)
            LDSM_X4(bfr[0][2*nj][0], bfr[0][2*nj][1], bfr[0][2*nj+1][0], bfr[0][2*nj+1][1],
                    bBase + nj*(16*SSTR*4));

        #pragma unroll
        for (int s = 0; s < 3; s++){
            const int nb = (s + 1) & 1;
            const int cb = s & 1;
            #pragma unroll
            for (int mi = 0; mi < 2; mi++)
                LDSM_X4(afr[nb][mi][0], afr[nb][mi][1], afr[nb][mi][2], afr[nb][mi][3],
                        aBase + mi*(16*SSTR*4) + (s+1)*32);
            #pragma unroll
            for (int nj = 0; nj < 4; nj++)
                LDSM_X4(bfr[nb][2*nj][0], bfr[nb][2*nj][1],
                        bfr[nb][2*nj+1][0], bfr[nb][2*nj+1][1],
                        bBase + nj*(16*SSTR*4) + (s+1)*32);
            #pragma unroll
            for (int mi = 0; mi < 2; mi++)
                #pragma unroll
                for (int ni = 0; ni < 8; ni++){
                    asm volatile(
                        "mma.sync.aligned.m16n8k16.row.col.f32.f16.f16.f32 "
                        "{%0,%1,%2,%3}, {%4,%5,%6,%7}, {%8,%9}, {%0,%1,%2,%3};\n"
                        : "+f"(acc[mi][ni][0]), "+f"(acc[mi][ni][1]),
                          "+f"(acc[mi][ni][2]), "+f"(acc[mi][ni][3])
                        : "r"(afr[cb][mi][0]), "r"(afr[cb][mi][1]),
                          "r"(afr[cb][mi][2]), "r"(afr[cb][mi][3]),
                          "r"(bfr[cb][ni][0]), "r"(bfr[cb][ni][1]));
                }
        }
        #pragma unroll
        for (int mi = 0; mi < 2; mi++)
            #pragma unroll
            for (int ni = 0; ni < 8; ni++){
                asm volatile(
                    "mma.sync.aligned.m16n8k16.row.col.f32.f16.f16.f32 "
                    "{%0,%1,%2,%3}, {%4,%5,%6,%7}, {%8,%9}, {%0,%1,%2,%3};\n"
                    : "+f"(acc[mi][ni][0]), "+f"(acc[mi][ni][1]),
                      "+f"(acc[mi][ni][2]), "+f"(acc[mi][ni][3])
                    : "r"(afr[1][mi][0]), "r"(afr[1][mi][1]),
                      "r"(afr[1][mi][2]), "r"(afr[1][mi][3]),
                      "r"(bfr[1][ni][0]), "r"(bfr[1][ni][1]));
            }
        __syncthreads();
    }

    // Epilogue: ReLU, fp16 store
    __half* Ch = (MODE == 0) ? g_dc : (MODE == 1) ? g_ph : g_m;
    #pragma unroll
    for (int mi = 0; mi < 2; mi++){
        int rbase = m0 + wm + mi*16 + g;
        #pragma unroll
        for (int half = 0; half < 2; half++){
            int t = rbase + half*8;
            if (t < NT){
                int col = n0 + wn + 2*c;
                #pragma unroll
                for (int ni = 0; ni < 8; ni++){
                    float x = fmaxf(acc[mi][ni][half*2 + 0], 0.f);
                    float y = fmaxf(acc[mi][ni][half*2 + 1], 0.f);
                    *reinterpret_cast<__half2*>(
                        Ch + (size_t)t*OUT + col + ni*8) = __floats2half2_rn(x, y);
                }
            }
        }
    }
}

// ---------------------------------------------------------------------------
// Final: out[b,s] = sequ_h[b,s] + (s<S-1 ? m[b,s] : 0) + (s>=2 ? m[b,s-1] : 0)
// Streaming (evict-first) stores: out is never re-read.
// ---------------------------------------------------------------------------
__global__ void final_k(float* __restrict__ out){
    int half = threadIdx.x / 96;
    int j    = threadIdx.x % 96;
    int t = blockIdx.x*2 + half;
    int s = t & (Sl - 1);
    int b = t >> 11;

    uint4 sqv = *reinterpret_cast<const uint4*>(g_sequ_h + (size_t)t*Hd + j*8);
    const __half2* sq = reinterpret_cast<const __half2*>(&sqv);
    float2 v[4];
    #pragma unroll
    for (int q = 0; q < 4; q++) v[q] = __half22float2(sq[q]);

    size_t mb = (size_t)b * (Sl - 1);
    if (s < Sl - 1){
        uint4 mv = *reinterpret_cast<const uint4*>(g_m + (mb + s)*Hd + j*8);
        const __half2* mp = reinterpret_cast<const __half2*>(&mv);
        #pragma unroll
        for (int q = 0; q < 4; q++){
            float2 f = __half22float2(mp[q]);
            v[q].x += f.x; v[q].y += f.y;
        }
    }
    if (s >= 2){
        uint4 mv = *reinterpret_cast<const uint4*>(g_m + (mb + s - 1)*Hd + j*8);
        const __half2* mp = reinterpret_cast<const __half2*>(&mv);
        #pragma unroll
        for (int q = 0; q < 4; q++){
            float2 f = __half22float2(mp[q]);
            v[q].x += f.x; v[q].y += f.y;
        }
    }
    float* op = out + (size_t)t*Hd + j*8;
    stg_cs16(op,     make_float4(v[0].x, v[0].y, v[1].x, v[1].y));
    stg_cs16(op + 4, make_float4(v[2].x, v[2].y, v[3].x, v[3].y));
}

// ---------------------------------------------------------------------------
// Launch: round-14 fork/join DAG (best measured schedule).
//   main: add_ue -> [wait Wprep] gemm1 -> [wait gemm0] gemm2 -> final
//   s1:   prep(all 5 tensors) -> gemm0
// ---------------------------------------------------------------------------
extern "C" void kernel_launch(void* const* d_in, const int* in_sizes, int n_in,
                              void* d_out, int out_size){
    const float* seqs  = (const float*)d_in[0];
    const int*   d_idx = (const int*)  d_in[1];
    const int*   c_idx = (const int*)  d_in[2];
    const int*   u_idx = (const int*)  d_in[3];
    const float* E_d   = (const float*)d_in[4];
    const float* E_c   = (const float*)d_in[5];
    const float* E_u   = (const float*)d_in[6];
    const float* W_cd  = (const float*)d_in[7];
    const float* W_hid = (const float*)d_in[8];
    const float* W_cdh = (const float*)d_in[9];
    float* out = (float*)d_out;

    static cudaStream_t s1 = nullptr;
    static cudaEvent_t evFork = nullptr, evPrep = nullptr, evG0 = nullptr;
    if (!s1){
        cudaStreamCreateWithFlags(&s1, cudaStreamNonBlocking);
        cudaEventCreateWithFlags(&evFork, cudaEventDisableTiming);
        cudaEventCreateWithFlags(&evPrep, cudaEventDisableTiming);
        cudaEventCreateWithFlags(&evG0,   cudaEventDisableTiming);

        cudaFuncSetAttribute(gemm_f16_k<0,256,128>,  cudaFuncAttributeMaxDynamicSharedMemorySize, SMEM_TOT);
        cudaFuncSetAttribute(gemm_f16_k<1,1536,768>, cudaFuncAttributeMaxDynamicSharedMemorySize, SMEM_TOT);
        cudaFuncSetAttribute(gemm_f16_k<2,896,768>,  cudaFuncAttributeMaxDynamicSharedMemorySize, SMEM_TOT);
    }

    __half *pEd, *pEc, *pWcd, *pWhid, *pWcdh;
    cudaGetSymbolAddress((void**)&pEd,   g_Ed);
    cudaGetSymbolAddress((void**)&pEc,   g_Ec);
    cudaGetSymbolAddress((void**)&pWcd,  g_Wcd);
    cudaGetSymbolAddress((void**)&pWhid, g_Whid);
    cudaGetSymbolAddress((void**)&pWcdh, g_Wcdh);

    const int MBLK = (NT + 127) / 128;   // 256

    // ---- fork
    cudaEventRecord(evFork, 0);
    cudaStreamWaitEvent(s1, evFork, 0);

    // s1: all weight/embedding prep in ONE launch (W tensors first), then gemm0
    {
        int n0 = 768*1536, n1 = 768*896, n2 = 128*256, n3 = 512*128, n4 = 512*128;
        halfquint_k<<<((n0+n1+n2+n3+n4)/4 + 255)/256, 256, 0, s1>>>(
            pWhid, W_hid, n0, pWcdh, W_cdh, n1, pWcd, W_cd, n2,
            pEd, E_d, n3, pEc, E_c, n4);
    }
    cudaEventRecord(evPrep, s1);
    gemm_f16_k<0, 256, 128><<<dim3(1, MBLK), 256, SMEM_TOT, s1>>>(d_idx, c_idx, pWcd);
    cudaEventRecord(evG0, s1);

    // main: add_ue (concurrent with prep)
    add_ue_k<<<NTOK_FULL/2, 192>>>(seqs, u_idx, E_u);

    // gemm1 needs Whid + add_ue
    cudaStreamWaitEvent(0, evPrep, 0);
    gemm_f16_k<1, 1536, 768><<<dim3(6, MBLK), 256, SMEM_TOT>>>(nullptr, nullptr, pWhid);

    // gemm2 needs gemm1 (stream order) + gemm0 (event join)
    cudaStreamWaitEvent(0, evG0, 0);
    gemm_f16_k<2, 896, 768><<<dim3(6, MBLK), 256, SMEM_TOT>>>(nullptr, nullptr, pWcdh);

    // final
    final_k<<<NTOK_FULL/2, 192>>>(out);
}